// round 1
// baseline (speedup 1.0000x reference)
#include <cuda_runtime.h>

// Fused 3-phase LSTM (centerline H=32 x100, encoder H=64 x20, decoder H=96 x30)
// Persistent block: 64 batch rows/CTA, weights + h in SMEM, c in registers.
// Matmuls via packed fp32 FFMA2 (fma.rn.f32x2): (i,f)/(g,o) gate pairs share a
// 64-bit lane; gate-interleaved SMEM weight layout Ws[k][j*4+g] makes one
// LDS.128 produce both packed weight operands.

#define TPB 512
#define BT  64

typedef unsigned long long ull;

// ---------------- packed f32x2 helpers ----------------
__device__ __forceinline__ ull pk2(float lo, float hi) {
    ull r; asm("mov.b64 %0, {%1, %2};" : "=l"(r) : "f"(lo), "f"(hi)); return r;
}
__device__ __forceinline__ ull dup2(float x) {
    ull r; asm("mov.b64 %0, {%1, %1};" : "=l"(r) : "f"(x)); return r;
}
__device__ __forceinline__ ull fma2(ull a, ull b, ull c) {
    ull d; asm("fma.rn.f32x2 %0, %1, %2, %3;" : "=l"(d) : "l"(a), "l"(b), "l"(c)); return d;
}
__device__ __forceinline__ float2 upk(ull a) {
    float lo, hi; asm("mov.b64 {%0, %1}, %2;" : "=f"(lo), "=f"(hi) : "l"(a));
    return make_float2(lo, hi);
}

// ---------------- fast activations (fp32-accurate enough for 1e-3) ----------------
__device__ __forceinline__ float fex2(float x){ float r; asm("ex2.approx.f32 %0, %1;" : "=f"(r) : "f"(x)); return r; }
__device__ __forceinline__ float frcp(float x){ float r; asm("rcp.approx.f32 %0, %1;" : "=f"(r) : "f"(x)); return r; }
__device__ __forceinline__ float sigm(float x){
    // 1/(1+exp(-x)); robust at extremes (rcp(inf)=0)
    return frcp(1.0f + fex2(-1.4426950408889634f * x));
}
__device__ __forceinline__ float tanh_(float x){
    return fmaf(2.0f, sigm(2.0f * x), -1.0f);
}

// ---------------- SMEM layout (floats) ----------------
#define WS_OFF    0        // weights, gate-interleaved: Ws[k*(4H) + j*4 + g]  (max 96*384 = 36864)
#define HS_OFF    36864    // h state: [96 rows][BT]   (enc rows 0..63, cent rows 64..95)
#define CS_OFF    43008    // c staging: [96][BT]
#define XS_OFF    49152    // x staging: 64 x float2
#define BPK_OFF   49280    // packed bias: [H][2] ull  (max 192 ull)
#define IPK_OFF   49664    // packed Wih:  [H][2 inp][2] ull (max 256 ull)
#define WEMB_OFF  50176    // W_emb packed: 96 x float2
#define BEMB_OFF  50368    // b_emb: 1 float2
#define SMEM_FLOATS 50372
#define SMEM_BYTES  (SMEM_FLOATS * 4)

// ---------------- weight/bias staging ----------------
template<int H>
__device__ __forceinline__ void load_W(float* __restrict__ Ws,
                                       const float* __restrict__ Whh,
                                       const float* __restrict__ Wih,  // nullptr or same-shape add (decoder)
                                       int tid)
{
    constexpr int total = 4 * H * H;
    for (int s = tid; s < total; s += TPB) {
        int row = s / H;            // 0..4H-1  (row = g*H + j)
        int k   = s - row * H;
        int g   = row / H;
        int j   = row - g * H;
        float v = Whh[s];
        if (Wih) v += Wih[s];
        Ws[k * (4 * H) + j * 4 + g] = v;
    }
}

template<int H>
__device__ __forceinline__ void load_bias(ull* __restrict__ Bpk,
                                          const float* __restrict__ bih,
                                          const float* __restrict__ bhh, int tid)
{
    for (int j = tid; j < H; j += TPB) {
        Bpk[j * 2 + 0] = pk2(bih[j] + bhh[j],             bih[H + j] + bhh[H + j]);
        Bpk[j * 2 + 1] = pk2(bih[2*H + j] + bhh[2*H + j], bih[3*H + j] + bhh[3*H + j]);
    }
}

template<int H>
__device__ __forceinline__ void load_ih(ull* __restrict__ Ipk,
                                        const float* __restrict__ Wih,  // [4H][2]
                                        int tid)
{
    for (int t = tid; t < 2 * H; t += TPB) {
        int j = t >> 1, inp = t & 1;
        Ipk[(j * 2 + inp) * 2 + 0] = pk2(Wih[(0*H + j) * 2 + inp], Wih[(1*H + j) * 2 + inp]);
        Ipk[(j * 2 + inp) * 2 + 1] = pk2(Wih[(2*H + j) * 2 + inp], Wih[(3*H + j) * 2 + inp]);
    }
}

// ---------------- gate matmul: gates += h @ W^T (packed pairs) ----------------
template<int H, int NH, int NB>
__device__ __forceinline__ void gates_mm(const float* __restrict__ Ws,
                                         const float* __restrict__ Hrows,  // this phase's h rows base
                                         int j0, int b0,
                                         ull (&aif)[NH][NB], ull (&ago)[NH][NB])
{
    const float* wbase = Ws + j0 * 4;
    const float* hbase = Hrows + b0;
    #pragma unroll 4
    for (int k = 0; k < H; k++) {
        ull hp[NB];
        if constexpr (NB == 4) {
            float4 hv = *(const float4*)(hbase + k * BT);
            hp[0] = dup2(hv.x); hp[1] = dup2(hv.y); hp[2] = dup2(hv.z); hp[3] = dup2(hv.w);
        } else {
            float2 hv = *(const float2*)(hbase + k * BT);
            hp[0] = dup2(hv.x); hp[1] = dup2(hv.y);
        }
        #pragma unroll
        for (int i = 0; i < NH; i++) {
            ulonglong2 w = *(const ulonglong2*)(wbase + k * (4 * H) + i * 4);
            #pragma unroll
            for (int b = 0; b < NB; b++) {
                aif[i][b] = fma2(w.x, hp[b], aif[i][b]);
                ago[i][b] = fma2(w.y, hp[b], ago[i][b]);
            }
        }
    }
}

// ---------------- activations + state update ----------------
template<int NH, int NB>
__device__ __forceinline__ void act_update(ull (&aif)[NH][NB], ull (&ago)[NH][NB],
                                           float (&cr)[NH][NB],
                                           float* __restrict__ Hw,  // &Hs[(HOFF+j0)*BT]
                                           int b0)
{
    #pragma unroll
    for (int i = 0; i < NH; i++) {
        #pragma unroll
        for (int b = 0; b < NB; b++) {
            float2 sif = upk(aif[i][b]);
            float2 sgo = upk(ago[i][b]);
            float ig = sigm(sif.x);
            float fg = sigm(sif.y);
            float gg = tanh_(sgo.x);
            float og = sigm(sgo.y);
            float cn = fmaf(fg, cr[i][b], ig * gg);
            cr[i][b] = cn;
            Hw[i * BT + b0 + b] = og * tanh_(cn);
        }
    }
}

// ---------------- input-driven LSTM phase (cent / enc) ----------------
template<int H, int NH, int NB, int HOFF, int T>
__device__ __forceinline__ void lstm_io_phase(float* __restrict__ S,
                                              const float* __restrict__ xsrc, int xstride,
                                              int B, int bbase, int tid)
{
    float*  Ws  = S + WS_OFF;
    float*  Hs  = S + HS_OFF;
    float*  Cs  = S + CS_OFF;
    float2* Xs  = (float2*)(S + XS_OFF);
    ull*    Bpk = (ull*)(S + BPK_OFF);
    ull*    Ipk = (ull*)(S + IPK_OFF);

    constexpr int BG = BT / NB;
    static_assert((H / NH) * BG == TPB, "thread map");
    int hg = tid / BG;
    int bg = tid % BG;
    int j0 = hg * NH, b0 = bg * NB;

    float cr[NH][NB];
    #pragma unroll
    for (int i = 0; i < NH; i++)
        #pragma unroll
        for (int b = 0; b < NB; b++) cr[i][b] = 0.0f;

    ull bif[NH], bgo[NH], wif0[NH], wif1[NH], wgo0[NH], wgo1[NH];
    #pragma unroll
    for (int i = 0; i < NH; i++) {
        bif[i]  = Bpk[(j0 + i) * 2 + 0];
        bgo[i]  = Bpk[(j0 + i) * 2 + 1];
        wif0[i] = Ipk[((j0 + i) * 2 + 0) * 2 + 0];
        wgo0[i] = Ipk[((j0 + i) * 2 + 0) * 2 + 1];
        wif1[i] = Ipk[((j0 + i) * 2 + 1) * 2 + 0];
        wgo1[i] = Ipk[((j0 + i) * 2 + 1) * 2 + 1];
    }

    const float* Hrows = Hs + HOFF * BT;
    float*       Hw    = Hs + (HOFF + j0) * BT;

    for (int t = 0; t < T; t++) {
        ull aif[NH][NB], ago[NH][NB];
        #pragma unroll
        for (int b = 0; b < NB; b++) {
            float2 x = Xs[b0 + b];
            ull x0 = dup2(x.x), x1 = dup2(x.y);
            #pragma unroll
            for (int i = 0; i < NH; i++) {
                aif[i][b] = fma2(wif0[i], x0, fma2(wif1[i], x1, bif[i]));
                ago[i][b] = fma2(wgo0[i], x0, fma2(wgo1[i], x1, bgo[i]));
            }
        }
        gates_mm<H, NH, NB>(Ws, Hrows, j0, b0, aif, ago);
        __syncthreads();                       // all h reads done
        act_update<NH, NB>(aif, ago, cr, Hw, b0);
        if (t + 1 < T && tid < BT) {           // stage x for next step
            int bb = bbase + tid; if (bb >= B) bb = B - 1;
            Xs[tid] = *(const float2*)&xsrc[(size_t)bb * xstride + (size_t)(t + 1) * 2];
        }
        __syncthreads();                       // new h + x visible
    }

    // stage final c into SMEM for the decoder
    #pragma unroll
    for (int i = 0; i < NH; i++)
        #pragma unroll
        for (int b = 0; b < NB; b++)
            Cs[(HOFF + j0 + i) * BT + b0 + b] = cr[i][b];
}

// ---------------- main fused kernel ----------------
__global__ void __launch_bounds__(TPB, 1)
lstm_fused_kernel(const float* __restrict__ traj,   // [B,20,2]
                  const float* __restrict__ cl,     // [B,100,2]
                  const float* __restrict__ Wih_c, const float* __restrict__ Whh_c,
                  const float* __restrict__ bih_c, const float* __restrict__ bhh_c,
                  const float* __restrict__ Wih_e, const float* __restrict__ Whh_e,
                  const float* __restrict__ bih_e, const float* __restrict__ bhh_e,
                  const float* __restrict__ Wih_d, const float* __restrict__ Whh_d,
                  const float* __restrict__ bih_d, const float* __restrict__ bhh_d,
                  const float* __restrict__ W_emb, const float* __restrict__ b_emb,
                  float* __restrict__ out, int B)
{
    extern __shared__ float S[];
    int tid   = threadIdx.x;
    int bbase = blockIdx.x * BT;

    float*  Ws   = S + WS_OFF;
    float*  Hs   = S + HS_OFF;
    float*  Cs   = S + CS_OFF;
    float2* Xs   = (float2*)(S + XS_OFF);
    ull*    Bpk  = (ull*)(S + BPK_OFF);
    ull*    Ipk  = (ull*)(S + IPK_OFF);
    float2* Wemb = (float2*)(S + WEMB_OFF);
    float2* Bemb = (float2*)(S + BEMB_OFF);

    // zero full h buffer (initial states)
    for (int s = tid; s < 96 * BT; s += TPB) Hs[s] = 0.0f;

    // ---- phase 1: centerline LSTM (H=32), h/c land in rows 64..95 ----
    load_W<32>(Ws, Whh_c, nullptr, tid);
    load_bias<32>(Bpk, bih_c, bhh_c, tid);
    load_ih<32>(Ipk, Wih_c, tid);
    if (tid < BT) {
        int bb = bbase + tid; if (bb >= B) bb = B - 1;
        Xs[tid] = *(const float2*)&cl[(size_t)bb * 200];
    }
    __syncthreads();
    lstm_io_phase<32, 2, 2, 64, 100>(S, cl, 200, B, bbase, tid);
    __syncthreads();

    // ---- phase 2: encoder LSTM (H=64), rows 0..63 ----
    load_W<64>(Ws, Whh_e, nullptr, tid);
    load_bias<64>(Bpk, bih_e, bhh_e, tid);
    load_ih<64>(Ipk, Wih_e, tid);
    if (tid < BT) {
        int bb = bbase + tid; if (bb >= B) bb = B - 1;
        Xs[tid] = *(const float2*)&traj[(size_t)bb * 40];
    }
    __syncthreads();
    lstm_io_phase<64, 2, 4, 0, 20>(S, traj, 40, B, bbase, tid);
    __syncthreads();

    // ---- phase 3: decoder LSTM (H=96), x == h so Wih+Whh fold ----
    load_W<96>(Ws, Whh_d, Wih_d, tid);
    load_bias<96>(Bpk, bih_d, bhh_d, tid);
    for (int k = tid; k < 96; k += TPB) Wemb[k] = make_float2(W_emb[k], W_emb[96 + k]);
    if (tid == 0) *Bemb = make_float2(b_emb[0], b_emb[1]);
    __syncthreads();

    {
        constexpr int NH = 3, NB = 4, BG = BT / NB;  // 32 hidden groups x 16 batch groups
        int hg = tid / BG, bg = tid % BG;
        int j0 = hg * NH, b0 = bg * NB;

        ull bif[NH], bgo[NH];
        float cr[NH][NB];
        #pragma unroll
        for (int i = 0; i < NH; i++) {
            bif[i] = Bpk[(j0 + i) * 2 + 0];
            bgo[i] = Bpk[(j0 + i) * 2 + 1];
        }
        #pragma unroll
        for (int i = 0; i < NH; i++)
            #pragma unroll
            for (int b = 0; b < NB; b++)
                cr[i][b] = Cs[(j0 + i) * BT + b0 + b];   // concat(enc_c, cent_c)

        for (int t = 0; t < 30; t++) {
            ull aif[NH][NB], ago[NH][NB];
            #pragma unroll
            for (int i = 0; i < NH; i++)
                #pragma unroll
                for (int b = 0; b < NB; b++) { aif[i][b] = bif[i]; ago[i][b] = bgo[i]; }

            gates_mm<96, NH, NB>(Ws, Hs, j0, b0, aif, ago);
            __syncthreads();                       // all h reads done
            act_update<NH, NB>(aif, ago, cr, Hs + j0 * BT, b0);
            __syncthreads();                       // new h visible

            // output projection: pos = h_new @ W_emb^T + b_emb  (2 outputs per row)
            if (tid < BT) {
                float2 acc = *Bemb;
                #pragma unroll 8
                for (int k = 0; k < 96; k++) {
                    float  h = Hs[k * BT + tid];
                    float2 w = Wemb[k];
                    acc.x = fmaf(h, w.x, acc.x);
                    acc.y = fmaf(h, w.y, acc.y);
                }
                int bb = bbase + tid;
                if (bb < B) *(float2*)&out[(size_t)(bb * 30 + t) * 2] = acc;
            }
            // no barrier needed: next gates_mm only READS Hs; the next write
            // happens after the next mid-step barrier, which projection threads
            // reach only after finishing their reads.
        }
    }
}

extern "C" void kernel_launch(void* const* d_in, const int* in_sizes, int n_in,
                              void* d_out, int out_size)
{
    const float* traj  = (const float*)d_in[0];
    const float* cl    = (const float*)d_in[1];
    const float* Wih_c = (const float*)d_in[2];
    const float* Whh_c = (const float*)d_in[3];
    const float* bih_c = (const float*)d_in[4];
    const float* bhh_c = (const float*)d_in[5];
    const float* Wih_e = (const float*)d_in[6];
    const float* Whh_e = (const float*)d_in[7];
    const float* bih_e = (const float*)d_in[8];
    const float* bhh_e = (const float*)d_in[9];
    const float* Wih_d = (const float*)d_in[10];
    const float* Whh_d = (const float*)d_in[11];
    const float* bih_d = (const float*)d_in[12];
    const float* bhh_d = (const float*)d_in[13];
    const float* W_emb = (const float*)d_in[14];
    const float* b_emb = (const float*)d_in[15];

    int B = in_sizes[0] / 40;             // input_traj is [B,20,2]
    int grid = (B + BT - 1) / BT;

    cudaFuncSetAttribute(lstm_fused_kernel,
                         cudaFuncAttributeMaxDynamicSharedMemorySize, SMEM_BYTES);
    lstm_fused_kernel<<<grid, TPB, SMEM_BYTES>>>(
        traj, cl, Wih_c, Whh_c, bih_c, bhh_c,
        Wih_e, Whh_e, bih_e, bhh_e,
        Wih_d, Whh_d, bih_d, bhh_d,
        W_emb, b_emb, (float*)d_out, B);
}